// round 5
// baseline (speedup 1.0000x reference)
#include <cuda_runtime.h>
#include <cstdint>

// Problem shape (fixed)
#define Bn   16
#define Tn   8192
#define Cn   128
#define NCH  256
#define CT   32           // Tn / NCH, fits one 32-bit mask register per channel
#define HC   64           // half-channels: threads per block, each owns 2 channels

// ---------------- device scratch (static; no allocations) ----------------
__device__ float2 g_locx[Bn * NCH * HC];
__device__ float2 g_locn[Bn * NCH * HC];
__device__ float2 g_incx[Bn * NCH * HC];
__device__ float2 g_incn[Bn * NCH * HC];
__device__ float2 g_locq[Bn * NCH * HC];
__device__ float2 g_incq[Bn * NCH * HC];
__device__ unsigned g_flag1[Bn * NCH];   // 0=none 1=local 2=inclusive
__device__ unsigned g_flag2[Bn * NCH];

// ---------------- helpers ----------------
__device__ __forceinline__ unsigned ld_acquire(const unsigned* p) {
    unsigned v;
    asm volatile("ld.acquire.gpu.u32 %0, [%1];" : "=r"(v) : "l"(p) : "memory");
    return v;
}
__device__ __forceinline__ void st_release(unsigned* p, unsigned v) {
    asm volatile("st.release.gpu.u32 [%0], %1;" :: "l"(p), "r"(v) : "memory");
}
__device__ __forceinline__ float frcp(float x) {
    float r; asm("rcp.approx.ftz.f32 %0, %1;" : "=f"(r) : "f"(x)); return r;
}
__device__ __forceinline__ float frsq(float x) {
    float r; asm("rsqrt.approx.ftz.f32 %0, %1;" : "=f"(r) : "f"(x)); return r;
}

__global__ void revin_init_flags() {
    int i = blockIdx.x * blockDim.x + threadIdx.x;
    if (i < Bn * NCH) { g_flag1[i] = 0u; g_flag2[i] = 0u; }
}

// ---------------- main kernel ----------------
// grid = (NCH, Bn), block = 64 threads; thread l owns channels (2l, 2l+1)
__global__ __launch_bounds__(HC) void revin_kernel(
    const float* __restrict__ x,
    const float* __restrict__ mask,
    float* __restrict__ out)
{
    const int k = blockIdx.x;           // chunk along T
    const int b = blockIdx.y;           // batch
    const int l = threadIdx.x;
    const int bN = b * NCH;

    const size_t base = (size_t)(b * Tn + k * CT) * Cn + 2 * l;
    const float2* __restrict__ px = (const float2*)(x    + base);
    const float2* __restrict__ pm = (const float2*)(mask + base);
    float2*       __restrict__ po = (float2*)(out + base);
    // per-timestep stride in float2 units = Cn/2 = HC

    const int ai = (bN + k) * HC + l;

    // ---------------- Phase 1: local sum of x; mask -> bits ----------------
    float2 Lx = make_float2(0.f, 0.f);
    unsigned mA = 0u, mB = 0u;   // bit t set => observed at timestep t
    #pragma unroll 8
    for (int t = 0; t < CT; ++t) {
        float2 xv = px[t * HC];
        float2 mv = pm[t * HC];
        Lx.x += xv.x; Lx.y += xv.y;
        mA |= (mv.x == 0.f ? 1u : 0u) << t;
        mB |= (mv.y == 0.f ? 1u : 0u) << t;
    }
    float2 Ln = make_float2((float)__popc(mA), (float)__popc(mB));

    g_locx[ai] = Lx;
    g_locn[ai] = Ln;
    __syncthreads();
    if (l == 0) { __threadfence(); st_release(&g_flag1[bN + k], 1u); }

    // ---------------- Lookback 1: backward scan, cut at first inclusive ----
    float2 exx = make_float2(0.f, 0.f);
    float2 exn = make_float2(0.f, 0.f);
    for (int j = k - 1; j >= 0; ) {
        const unsigned* fp = &g_flag1[bN + j];
        unsigned f = ld_acquire(fp);
        while (f == 0u) { __nanosleep(20); f = ld_acquire(fp); }
        f = __shfl_sync(0xffffffffu, f, 0);   // uniform decision per warp
        const int idx = (bN + j) * HC + l;
        if (f == 2u) {
            float2 a = g_incx[idx], n = g_incn[idx];
            exx.x += a.x; exx.y += a.y; exn.x += n.x; exn.y += n.y;
            break;
        }
        float2 a = g_locx[idx], n = g_locn[idx];
        exx.x += a.x; exx.y += a.y; exn.x += n.x; exn.y += n.y;
        --j;
    }
    // publish inclusive
    g_incx[ai] = make_float2(exx.x + Lx.x, exx.y + Lx.y);
    g_incn[ai] = make_float2(exn.x + Ln.x, exn.y + Ln.y);
    __syncthreads();
    if (l == 0) { __threadfence(); st_release(&g_flag1[bN + k], 2u); }

    // ---------------- Phase 2: running mean; local Ssq ----------------
    float2 sx = exx, sn = exn;
    float2 lsq = make_float2(0.f, 0.f);
    #pragma unroll 8
    for (int t = 0; t < CT; ++t) {
        float2 xv = px[t * HC];
        float nm, nn, mean, d;

        nm = (float)((mA >> t) & 1u);
        sx.x += xv.x; sn.x += nm;
        nn = (sn.x == 0.f) ? 1.f : sn.x;
        mean = sx.x * frcp(nn);
        d = (xv.x - mean) * nm;
        lsq.x = fmaf(d, d, lsq.x);

        nm = (float)((mB >> t) & 1u);
        sx.y += xv.y; sn.y += nm;
        nn = (sn.y == 0.f) ? 1.f : sn.y;
        mean = sx.y * frcp(nn);
        d = (xv.y - mean) * nm;
        lsq.y = fmaf(d, d, lsq.y);
    }
    g_locq[ai] = lsq;
    __syncthreads();
    if (l == 0) { __threadfence(); st_release(&g_flag2[bN + k], 1u); }

    // ---------------- Lookback 2 ----------------
    float2 exq = make_float2(0.f, 0.f);
    for (int j = k - 1; j >= 0; ) {
        const unsigned* fp = &g_flag2[bN + j];
        unsigned f = ld_acquire(fp);
        while (f == 0u) { __nanosleep(20); f = ld_acquire(fp); }
        f = __shfl_sync(0xffffffffu, f, 0);
        const int idx = (bN + j) * HC + l;
        if (f == 2u) {
            float2 q = g_incq[idx];
            exq.x += q.x; exq.y += q.y;
            break;
        }
        float2 q = g_locq[idx];
        exq.x += q.x; exq.y += q.y;
        --j;
    }
    g_incq[ai] = make_float2(exq.x + lsq.x, exq.y + lsq.y);
    __syncthreads();
    if (l == 0) { __threadfence(); st_release(&g_flag2[bN + k], 2u); }

    // ---------------- Phase 3: output ----------------
    sx = exx; sn = exn;
    float2 ssq = exq;
    #pragma unroll 8
    for (int t = 0; t < CT; ++t) {
        float2 xv = px[t * HC];
        float2 o;
        float nm, nn, rcpn, mean, d, var, inv, ov;

        nm = (float)((mA >> t) & 1u);
        sx.x += xv.x; sn.x += nm;
        nn = (sn.x == 0.f) ? 1.f : sn.x;
        rcpn = frcp(nn);
        mean = sx.x * rcpn;
        d = (xv.x - mean) * nm;
        ssq.x = fmaf(d, d, ssq.x);
        var = ssq.x * rcpn;
        inv = (var > 1e-10f) ? frsq(var) : 1.f;
        ov = (xv.x - mean) * inv;
        o.x = fminf(fmaxf(ov, -100.f), 100.f);

        nm = (float)((mB >> t) & 1u);
        sx.y += xv.y; sn.y += nm;
        nn = (sn.y == 0.f) ? 1.f : sn.y;
        rcpn = frcp(nn);
        mean = sx.y * rcpn;
        d = (xv.y - mean) * nm;
        ssq.y = fmaf(d, d, ssq.y);
        var = ssq.y * rcpn;
        inv = (var > 1e-10f) ? frsq(var) : 1.f;
        ov = (xv.y - mean) * inv;
        o.y = fminf(fmaxf(ov, -100.f), 100.f);

        po[t * HC] = o;
    }
}

// ---------------- launch ----------------
extern "C" void kernel_launch(void* const* d_in, const int* in_sizes, int n_in,
                              void* d_out, int out_size)
{
    const float* x    = (const float*)d_in[0];
    const float* mask = (const float*)d_in[1];
    float* out        = (float*)d_out;

    revin_init_flags<<<(Bn * NCH + 511) / 512, 512>>>();
    dim3 grid(NCH, Bn);
    revin_kernel<<<grid, HC>>>(x, mask, out);
}

// round 6
// speedup vs baseline: 1.4337x; 1.4337x over previous
#include <cuda_runtime.h>
#include <cstdint>

// Problem shape (fixed)
#define Bn   16
#define Tn   8192
#define Cn   128
#define NCH  128           // chunks along T
#define CT   64            // timesteps per chunk
#define HT   32            // timesteps per half-chunk (one mask register)
#define HC   64            // float2 lanes per half (2 channels/thread)

// ---------------- device scratch (static; no allocations) ----------------
__device__ float2 g_aggx [Bn * NCH * HC];   // per-chunk local sum of x
__device__ float2 g_aggn [Bn * NCH * HC];   // per-chunk local count of observed
__device__ float2 g_aggq [Bn * NCH * HC];   // per-chunk local sum of term^2
__device__ unsigned g_flags[2 * Bn * NCH];  // [0..]=phase1, [Bn*NCH..]=phase2

// ---------------- helpers ----------------
__device__ __forceinline__ unsigned ld_acquire(const unsigned* p) {
    unsigned v;
    asm volatile("ld.acquire.gpu.u32 %0, [%1];" : "=r"(v) : "l"(p) : "memory");
    return v;
}
__device__ __forceinline__ void st_release(unsigned* p, unsigned v) {
    asm volatile("st.release.gpu.u32 [%0], %1;" :: "l"(p), "r"(v) : "memory");
}
__device__ __forceinline__ float frcp(float x) {
    float r; asm("rcp.approx.ftz.f32 %0, %1;" : "=f"(r) : "f"(x)); return r;
}
__device__ __forceinline__ float frsq(float x) {
    float r; asm("rsqrt.approx.ftz.f32 %0, %1;" : "=f"(r) : "f"(x)); return r;
}

__global__ void revin_init_flags() {
    int i = blockIdx.x * blockDim.x + threadIdx.x;
    if (i < 2 * Bn * NCH) g_flags[i] = 0u;
}

// ---------------- main kernel ----------------
// grid = (NCH, Bn), block = 128 threads.
// h = tid>>6 selects time-half; l = tid&63 selects channel pair (2l, 2l+1).
__global__ __launch_bounds__(128) void revin_kernel(
    const float* __restrict__ x,
    const float* __restrict__ mask,
    float* __restrict__ out)
{
    __shared__ float2 s_h0x[HC], s_h0n[HC], s_h0q[HC];  // half0 locals
    __shared__ float2 s_pa[2][HC], s_pb[2][HC];         // lookback partials

    const int tid = threadIdx.x;
    const int h = tid >> 6;
    const int l = tid & 63;
    const int k = blockIdx.x;            // chunk along T
    const int b = blockIdx.y;            // batch
    const int bN = b * NCH;

    const size_t base = (size_t)((b * Tn + k * CT + h * HT) * Cn) + 2 * l;
    const float2* __restrict__ px = (const float2*)(x    + base);
    const float2* __restrict__ pm = (const float2*)(mask + base);
    float2*       __restrict__ po = (float2*)(out + base);
    // per-timestep stride in float2 units = Cn/2 = 64

    unsigned* flagsA = g_flags + bN;
    unsigned* flagsB = g_flags + Bn * NCH + bN;
    const int ai = (bN + k) * HC + l;

    // ---------------- Phase 1: half-local sum of x; mask -> bits ----------------
    float2 Lx = make_float2(0.f, 0.f);
    unsigned mA = 0u, mB = 0u;       // bit t set => observed at local timestep t
    #pragma unroll 8
    for (int t = 0; t < HT; ++t) {
        float2 xv = px[t * 64];
        float2 mv = pm[t * 64];
        Lx.x += xv.x; Lx.y += xv.y;
        mA |= (unsigned)(mv.x == 0.f) << t;
        mB |= (unsigned)(mv.y == 0.f) << t;
    }
    float2 Ln = make_float2((float)__popc(mA), (float)__popc(mB));

    if (h == 0) { s_h0x[l] = Lx; s_h0n[l] = Ln; }
    __syncthreads();
    if (h == 1) {
        float2 h0x = s_h0x[l], h0n = s_h0n[l];
        g_aggx[ai] = make_float2(h0x.x + Lx.x, h0x.y + Lx.y);
        g_aggn[ai] = make_float2(h0n.x + Ln.x, h0n.y + Ln.y);
    }
    __syncthreads();
    if (tid == 0) { __threadfence(); st_release(&flagsA[k], 1u); }

    // ---------------- Lookback 1: parallel wait, parity-split sum ----------------
    if (tid < k) {
        while (ld_acquire(&flagsA[tid]) == 0u) __nanosleep(40);
    }
    __syncthreads();

    {
        float2 pxs = make_float2(0.f, 0.f), pns = make_float2(0.f, 0.f);
        #pragma unroll 4
        for (int j = h; j < k; j += 2) {
            float2 a = g_aggx[(bN + j) * HC + l];
            float2 n = g_aggn[(bN + j) * HC + l];
            pxs.x += a.x; pxs.y += a.y;
            pns.x += n.x; pns.y += n.y;
        }
        s_pa[h][l] = pxs; s_pb[h][l] = pns;
    }
    __syncthreads();

    float2 exx, exn;   // chunk-exclusive (Sx, Sn)
    {
        float2 a0 = s_pa[0][l], a1 = s_pa[1][l];
        float2 n0 = s_pb[0][l], n1 = s_pb[1][l];
        exx = make_float2(a0.x + a1.x, a0.y + a1.y);
        exn = make_float2(n0.x + n1.x, n0.y + n1.y);
    }
    // this thread's starting state (half1 adds half0's local)
    float2 ssx = exx, ssn = exn;
    if (h == 1) {
        float2 h0x = s_h0x[l], h0n = s_h0n[l];
        ssx.x += h0x.x; ssx.y += h0x.y;
        ssn.x += h0n.x; ssn.y += h0n.y;
    }

    // ---------------- Phase 2: running mean; half-local Ssq ----------------
    float2 sx = ssx, sn = ssn;
    float2 lsq = make_float2(0.f, 0.f);
    #pragma unroll 8
    for (int t = 0; t < HT; ++t) {
        float2 xv = px[t * 64];
        float nm, nn, mean, d;

        nm = (float)((mA >> t) & 1u);
        sx.x += xv.x; sn.x += nm;
        nn = (sn.x == 0.f) ? 1.f : sn.x;
        mean = sx.x * frcp(nn);
        d = (xv.x - mean) * nm;
        lsq.x = fmaf(d, d, lsq.x);

        nm = (float)((mB >> t) & 1u);
        sx.y += xv.y; sn.y += nm;
        nn = (sn.y == 0.f) ? 1.f : sn.y;
        mean = sx.y * frcp(nn);
        d = (xv.y - mean) * nm;
        lsq.y = fmaf(d, d, lsq.y);
    }

    if (h == 0) { s_h0q[l] = lsq; }
    __syncthreads();
    if (h == 1) {
        float2 h0q = s_h0q[l];
        g_aggq[ai] = make_float2(h0q.x + lsq.x, h0q.y + lsq.y);
    }
    __syncthreads();
    if (tid == 0) { __threadfence(); st_release(&flagsB[k], 1u); }

    // ---------------- Lookback 2 ----------------
    if (tid < k) {
        while (ld_acquire(&flagsB[tid]) == 0u) __nanosleep(40);
    }
    __syncthreads();

    {
        float2 pq = make_float2(0.f, 0.f);
        #pragma unroll 4
        for (int j = h; j < k; j += 2) {
            float2 q = g_aggq[(bN + j) * HC + l];
            pq.x += q.x; pq.y += q.y;
        }
        s_pa[h][l] = pq;
    }
    __syncthreads();

    float2 ssq;
    {
        float2 q0 = s_pa[0][l], q1 = s_pa[1][l];
        ssq = make_float2(q0.x + q1.x, q0.y + q1.y);
    }
    if (h == 1) {
        float2 h0q = s_h0q[l];
        ssq.x += h0q.x; ssq.y += h0q.y;
    }

    // ---------------- Phase 3: output ----------------
    sx = ssx; sn = ssn;
    #pragma unroll 8
    for (int t = 0; t < HT; ++t) {
        float2 xv = px[t * 64];
        float2 o;
        float nm, nn, rcpn, mean, d, var, inv, ov;

        nm = (float)((mA >> t) & 1u);
        sx.x += xv.x; sn.x += nm;
        nn = (sn.x == 0.f) ? 1.f : sn.x;
        rcpn = frcp(nn);
        mean = sx.x * rcpn;
        d = (xv.x - mean) * nm;
        ssq.x = fmaf(d, d, ssq.x);
        var = ssq.x * rcpn;
        inv = (var > 1e-10f) ? frsq(var) : 1.f;   // std>1e-5 <=> var>1e-10
        ov = (xv.x - mean) * inv;
        o.x = fminf(fmaxf(ov, -100.f), 100.f);

        nm = (float)((mB >> t) & 1u);
        sx.y += xv.y; sn.y += nm;
        nn = (sn.y == 0.f) ? 1.f : sn.y;
        rcpn = frcp(nn);
        mean = sx.y * rcpn;
        d = (xv.y - mean) * nm;
        ssq.y = fmaf(d, d, ssq.y);
        var = ssq.y * rcpn;
        inv = (var > 1e-10f) ? frsq(var) : 1.f;
        ov = (xv.y - mean) * inv;
        o.y = fminf(fmaxf(ov, -100.f), 100.f);

        po[t * 64] = o;
    }
}

// ---------------- launch ----------------
extern "C" void kernel_launch(void* const* d_in, const int* in_sizes, int n_in,
                              void* d_out, int out_size)
{
    const float* x    = (const float*)d_in[0];
    const float* mask = (const float*)d_in[1];
    float* out        = (float*)d_out;

    revin_init_flags<<<(2 * Bn * NCH + 511) / 512, 512>>>();
    dim3 grid(NCH, Bn);
    revin_kernel<<<grid, 128>>>(x, mask, out);
}